// round 16
// baseline (speedup 1.0000x reference)
#include <cuda_runtime.h>

#define N 128
#define D 8192
#define KSLICES 256
#define KSLICE (D / KSLICES)   // 32
#define KCHUNK 16
#define NCHUNKS (KSLICE / KCHUNK)  // 2

typedef unsigned long long ull;

__device__ float g_sq1[N], g_sq2[N];
__device__ float g_part[KSLICES * N * N];
__device__ float g_GM[N * N];
__device__ int   g_flag;           // nonzero => cross-label GM entry != 0

// ---------------------------------------------------------------------------
// K1: fused split-K GEMM + row norms.
// grid (1,1,264): z<256 -> GEMM: full 128x128 tile, 32-K slice, 256 threads,
//   8x8 outputs/thread, transposed smem [k][i], f32x2 FMA, double-buffered.
//   2 CTAs resident per SM (16 warps) for latency hiding.
//   z>=256 -> 8 norm blocks (32 rows each, warp per 4 rows).
// ---------------------------------------------------------------------------
__global__ void __launch_bounds__(256, 2) dotsq_kernel(const float* __restrict__ f1,
                                                       const float* __restrict__ f2) {
    if (blockIdx.z >= KSLICES) {
        // ---- norm path ----
        int flat = blockIdx.z - KSLICES;      // 0..7
        int tid  = threadIdx.x;
        int wid  = tid >> 5, lane = tid & 31;
        if (flat == 0 && tid == 0) g_flag = 0;
        #pragma unroll
        for (int rr = 0; rr < 4; rr++) {
            int row = flat * 32 + wid * 4 + rr;   // 0..255
            const float* f = (row < N) ? (f1 + (size_t)row * D)
                                       : (f2 + (size_t)(row - N) * D);
            const float4* f4 = (const float4*)f;
            float s = 0.f;
            #pragma unroll 8
            for (int it = 0; it < D / 4 / 32; it++) {
                float4 v = f4[lane + it * 32];
                s += v.x * v.x + v.y * v.y + v.z * v.z + v.w * v.w;
            }
            #pragma unroll
            for (int o = 16; o; o >>= 1) s += __shfl_xor_sync(0xffffffffu, s, o);
            if (lane == 0) { if (row < N) g_sq1[row] = s; else g_sq2[row - N] = s; }
        }
        return;
    }

    // ---- GEMM path: C[128][128] += A[128][32] * B[128][32]^T (this slice) ----
    __shared__ float As[2][KCHUNK][128];   // [k][i], i contiguous
    __shared__ float Bs[2][KCHUNK][128];   // [k][j], j contiguous

    int tid = threadIdx.x;                 // 0..255
    int ix = tid & 15;                     // i group: rows ix*4..+3 and +64
    int jy = tid >> 4;                     // j group: cols jy*4..+3 and +64
    int k0 = blockIdx.z * KSLICE;

    int lrow = tid & 127;                  // load row (i or j)
    int lkq  = (tid >> 7) * 4;             // load k offset (0 or 4)

    ull acc[8][4];
    #pragma unroll
    for (int m = 0; m < 8; m++)
        #pragma unroll
        for (int p = 0; p < 4; p++) acc[m][p] = 0ull;

    // prolog: load + stage chunk 0
    float4 pa0 = *(const float4*)&f1[(size_t)lrow * D + k0 + lkq];
    float4 pa1 = *(const float4*)&f1[(size_t)lrow * D + k0 + lkq + 8];
    float4 pb0 = *(const float4*)&f2[(size_t)lrow * D + k0 + lkq];
    float4 pb1 = *(const float4*)&f2[(size_t)lrow * D + k0 + lkq + 8];
    As[0][lkq + 0][lrow] = pa0.x; As[0][lkq + 1][lrow] = pa0.y;
    As[0][lkq + 2][lrow] = pa0.z; As[0][lkq + 3][lrow] = pa0.w;
    As[0][lkq + 8][lrow] = pa1.x; As[0][lkq + 9][lrow] = pa1.y;
    As[0][lkq + 10][lrow] = pa1.z; As[0][lkq + 11][lrow] = pa1.w;
    Bs[0][lkq + 0][lrow] = pb0.x; Bs[0][lkq + 1][lrow] = pb0.y;
    Bs[0][lkq + 2][lrow] = pb0.z; Bs[0][lkq + 3][lrow] = pb0.w;
    Bs[0][lkq + 8][lrow] = pb1.x; Bs[0][lkq + 9][lrow] = pb1.y;
    Bs[0][lkq + 10][lrow] = pb1.z; Bs[0][lkq + 11][lrow] = pb1.w;
    __syncthreads();

    #pragma unroll
    for (int c = 0; c < NCHUNKS; c++) {
        int buf = c & 1;
        // prefetch next chunk to registers
        if (c + 1 < NCHUNKS) {
            int kc = k0 + (c + 1) * KCHUNK + lkq;
            pa0 = *(const float4*)&f1[(size_t)lrow * D + kc];
            pa1 = *(const float4*)&f1[(size_t)lrow * D + kc + 8];
            pb0 = *(const float4*)&f2[(size_t)lrow * D + kc];
            pb1 = *(const float4*)&f2[(size_t)lrow * D + kc + 8];
        }

        #pragma unroll
        for (int k = 0; k < KCHUNK; k++) {
            float4 alo = *(const float4*)&As[buf][k][ix * 4];
            float4 ahi = *(const float4*)&As[buf][k][ix * 4 + 64];
            float4 blo = *(const float4*)&Bs[buf][k][jy * 4];
            float4 bhi = *(const float4*)&Bs[buf][k][jy * 4 + 64];
            ull b01, b23, b45, b67;
            asm("mov.b64 %0, {%1, %2};" : "=l"(b01) : "f"(blo.x), "f"(blo.y));
            asm("mov.b64 %0, {%1, %2};" : "=l"(b23) : "f"(blo.z), "f"(blo.w));
            asm("mov.b64 %0, {%1, %2};" : "=l"(b45) : "f"(bhi.x), "f"(bhi.y));
            asm("mov.b64 %0, {%1, %2};" : "=l"(b67) : "f"(bhi.z), "f"(bhi.w));
            float av[8] = {alo.x, alo.y, alo.z, alo.w, ahi.x, ahi.y, ahi.z, ahi.w};
            #pragma unroll
            for (int m = 0; m < 8; m++) {
                ull aa;
                asm("mov.b64 %0, {%1, %1};" : "=l"(aa) : "f"(av[m]));
                asm("fma.rn.f32x2 %0, %1, %2, %0;" : "+l"(acc[m][0]) : "l"(aa), "l"(b01));
                asm("fma.rn.f32x2 %0, %1, %2, %0;" : "+l"(acc[m][1]) : "l"(aa), "l"(b23));
                asm("fma.rn.f32x2 %0, %1, %2, %0;" : "+l"(acc[m][2]) : "l"(aa), "l"(b45));
                asm("fma.rn.f32x2 %0, %1, %2, %0;" : "+l"(acc[m][3]) : "l"(aa), "l"(b67));
            }
        }
        __syncthreads();

        if (c + 1 < NCHUNKS) {
            int nb = (c + 1) & 1;
            As[nb][lkq + 0][lrow] = pa0.x; As[nb][lkq + 1][lrow] = pa0.y;
            As[nb][lkq + 2][lrow] = pa0.z; As[nb][lkq + 3][lrow] = pa0.w;
            As[nb][lkq + 8][lrow] = pa1.x; As[nb][lkq + 9][lrow] = pa1.y;
            As[nb][lkq + 10][lrow] = pa1.z; As[nb][lkq + 11][lrow] = pa1.w;
            Bs[nb][lkq + 0][lrow] = pb0.x; Bs[nb][lkq + 1][lrow] = pb0.y;
            Bs[nb][lkq + 2][lrow] = pb0.z; Bs[nb][lkq + 3][lrow] = pb0.w;
            Bs[nb][lkq + 8][lrow] = pb1.x; Bs[nb][lkq + 9][lrow] = pb1.y;
            Bs[nb][lkq + 10][lrow] = pb1.z; Bs[nb][lkq + 11][lrow] = pb1.w;
            __syncthreads();
        }
    }

    // epilogue: unpack and store
    #pragma unroll
    for (int m = 0; m < 8; m++) {
        int gi = (m < 4) ? (ix * 4 + m) : (ix * 4 + 64 + (m - 4));
        float4 o;
        float lo, hi;
        asm("mov.b64 {%0,%1}, %2;" : "=f"(lo), "=f"(hi) : "l"(acc[m][0])); o.x = lo; o.y = hi;
        asm("mov.b64 {%0,%1}, %2;" : "=f"(lo), "=f"(hi) : "l"(acc[m][1])); o.z = lo; o.w = hi;
        *(float4*)&g_part[blockIdx.z * (N * N) + (size_t)gi * N + jy * 4] = o;
        asm("mov.b64 {%0,%1}, %2;" : "=f"(lo), "=f"(hi) : "l"(acc[m][2])); o.x = lo; o.y = hi;
        asm("mov.b64 {%0,%1}, %2;" : "=f"(lo), "=f"(hi) : "l"(acc[m][3])); o.z = lo; o.w = hi;
        *(float4*)&g_part[blockIdx.z * (N * N) + (size_t)gi * N + jy * 4 + 64] = o;
    }
}

// ---------------------------------------------------------------------------
// K2: finalize GM[i][j]; flag if any cross-label GM entry is nonzero.
// 128 blocks x 128 threads; each thread sums 256 partials (coalesced/slice).
// ---------------------------------------------------------------------------
__global__ void gm_kernel(const int* __restrict__ t1, const int* __restrict__ t2) {
    int idx = blockIdx.x * 128 + threadIdx.x;
    int i = idx >> 7, j = idx & (N - 1);
    float dot = 0.f;
    #pragma unroll 16
    for (int s = 0; s < KSLICES; s++) dot += g_part[s * (N * N) + idx];
    float d2 = g_sq1[i] - 2.f * dot + g_sq2[j];
    bool same = (t1[i] == t2[j]);
    float gm = same ? fmaxf(0.f, d2) : fmaxf(0.f, 200.f - d2);
    g_GM[idx] = gm;
    if (!same && gm != 0.f) atomicOr(&g_flag, 1);
}

// ---------------------------------------------------------------------------
// order-preserving float <-> u32 keys for min reductions
// ---------------------------------------------------------------------------
__device__ __forceinline__ unsigned fkey(float f) {
    unsigned u = __float_as_uint(f);
    return (u & 0x80000000u) ? ~u : (u | 0x80000000u);
}

// ---------------------------------------------------------------------------
// K3: block-decomposed assignment (one warp per label, 16 warps in one CTA).
// Dijkstra step: winner lane packed into the REDUX key (no ballot); exact
// dmin recovered via shfl from the winner. Warp 0 runs the full 128x128
// fallback if the precondition fails.
// ---------------------------------------------------------------------------
__global__ void assign_kernel(const int* __restrict__ t1, const int* __restrict__ t2,
                              float* __restrict__ out) {
    extern __shared__ unsigned char raw[];
    float* tile    = (float*)raw;                 // 16 * 1024 floats (64 KB)
    int*   rows    = (int*)(tile + 16 * 1024);    // 16 * 32 (fallback: rm_s)
    int*   cols    = rows + 16 * 32;              // 16 * 32
    float* u_all   = (float*)(cols + 16 * 32);    // 16 * 34 (fallback: u_s)
    int*   p_all   = (int*)(u_all + 16 * 34);     // 16 * 34 (fallback: p_s)
    int*   way_all = p_all + 16 * 34;             // 16 * 34 (fallback: way_s)
    int*   t1s     = way_all + 16 * 34;           // 128
    int*   t2s     = t1s + 128;                   // 128
    int*   rc      = t2s + 128;                   // 32
    float* vals    = (float*)(rc + 32);           // 16
    int*   s_need  = (int*)(vals + 16);           // 1

    const unsigned FULL = 0xffffffffu;
    int tid = threadIdx.x, lane = tid & 31, w = tid >> 5;

    if (tid < 128) { t1s[tid] = t1[tid]; t2s[tid] = t2[tid]; }
    __syncthreads();

    int r = 0, c = 0;
    #pragma unroll
    for (int ch = 0; ch < 4; ch++) {
        int e1 = t1s[ch * 32 + lane];
        unsigned b1 = __ballot_sync(FULL, e1 == w);
        if (e1 == w) {
            int pos = r + __popc(b1 & ((1u << lane) - 1u));
            if (pos < 32) rows[w * 32 + pos] = ch * 32 + lane;
        }
        r += __popc(b1);
        int e2 = t2s[ch * 32 + lane];
        unsigned b2 = __ballot_sync(FULL, e2 == w);
        if (e2 == w) {
            int pos = c + __popc(b2 & ((1u << lane) - 1u));
            if (pos < 32) cols[w * 32 + pos] = ch * 32 + lane;
        }
        c += __popc(b2);
    }
    if (lane == 0) { rc[w * 2] = r; rc[w * 2 + 1] = c; }
    __syncthreads();

    if (tid == 0) {
        int need = (g_flag != 0);
        int sr = 0, sc = 0;
        for (int L = 0; L < 16; L++) {
            int rr = rc[L * 2], cc = rc[L * 2 + 1];
            sr += rr; sc += cc;
            if (rr > 32 || cc > 32) need = 1;
        }
        if (sr != N || sc != N) need = 1;
        s_need[0] = need;
    }
    __syncthreads();

    // ---------------- fallback: full 128x128 single-warp Hungarian ----------
    if (s_need[0]) {
        if (w != 0) return;
        float* cost  = tile;
        float* u_s   = u_all;
        int*   p_s   = p_all;
        int*   way_s = way_all;
        int*   rm_s  = rows;

        for (int idx = lane; idx < N * N; idx += 32) cost[idx] = -g_GM[idx];
        for (int idx = lane; idx <= N; idx += 32) { p_s[idx] = 0; way_s[idx] = 0; rm_s[idx] = 0; }
        __syncwarp();

        #pragma unroll
        for (int t = 0; t < 4; t++) {
            int rr = lane + 32 * t;
            float m = 1e30f;
            #pragma unroll 4
            for (int cc = 0; cc < N; cc++) {
                int ccc = (cc + lane) & (N - 1);
                m = fminf(m, cost[rr * N + ccc]);
            }
            u_s[rr + 1] = m;
        }
        __syncwarp();

        float v4[4];
        #pragma unroll
        for (int t = 0; t < 4; t++) {
            int cc = lane + 32 * t;
            float m = 1e30f;
            for (int rr = 0; rr < N; rr++) m = fminf(m, cost[rr * N + cc] - u_s[rr + 1]);
            v4[t] = m;
        }
        __syncwarp();

        for (int i = 1; i <= N; i++) {
            unsigned cand = 0xffffffffu;
            float ui = u_s[i];
            #pragma unroll
            for (int t = 0; t < 4; t++) {
                int cc = lane + 32 * t;
                if (p_s[cc + 1] == 0) {
                    float cur = (cost[(i - 1) * N + cc] - ui) - v4[t];
                    if (cur <= 0.0f) cand = min(cand, (unsigned)cc);
                }
            }
            unsigned cm = __reduce_min_sync(FULL, cand);
            if (cm != 0xffffffffu && lane == 0) { p_s[cm + 1] = i; rm_s[i] = 1; }
            __syncwarp();
        }

        for (int i = 1; i <= N; i++) {
            if (rm_s[i]) continue;
            float minv[4] = {1e30f, 1e30f, 1e30f, 1e30f};
            unsigned usedmask = 0;
            if (lane == 0) p_s[0] = i;
            int j0 = 0;
            __syncwarp();

            for (int guard = 0; guard < N + 2; guard++) {
                if (j0 > 0) {
                    int cc = j0 - 1;
                    if ((cc & 31) == lane) usedmask |= 1u << (cc >> 5);
                }
                int i0 = p_s[j0];
                float ui0 = u_s[i0];
                float best = 1e30f; int bestc = 0;
                #pragma unroll
                for (int t = 0; t < 4; t++) {
                    if (!((usedmask >> t) & 1)) {
                        int cc = lane + 32 * t;
                        float cur = (cost[(i0 - 1) * N + cc] - ui0) - v4[t];
                        if (cur < minv[t]) { minv[t] = cur; way_s[cc + 1] = j0; }
                        if (minv[t] < best) { best = minv[t]; bestc = cc; }
                    }
                }
                unsigned key = fkey(best);
                unsigned rmin = __reduce_min_sync(FULL, key);
                unsigned ball = __ballot_sync(FULL, key == rmin);
                int win = __ffs(ball) - 1;
                float delta = __shfl_sync(FULL, best, win);
                int j1 = __shfl_sync(FULL, bestc, win) + 1;

                #pragma unroll
                for (int t = 0; t < 4; t++) {
                    if ((usedmask >> t) & 1) {
                        v4[t] -= delta;
                        int pr = p_s[lane + 32 * t + 1];
                        u_s[pr] += delta;
                    } else {
                        minv[t] -= delta;
                    }
                }
                if (lane == 0) u_s[i] += delta;
                j0 = j1;
                __syncwarp();
                if (p_s[j0] == 0) break;
            }

            if (lane == 0) {
                int jj = j0;
                while (jj) { int j1 = way_s[jj]; p_s[jj] = p_s[j1]; jj = j1; }
                rm_s[i] = 1;
            }
            __syncwarp();
        }

        float s = 0.f;
        #pragma unroll
        for (int t = 0; t < 4; t++) {
            int cc = lane + 32 * t;
            int rr = p_s[cc + 1];
            s += cost[(rr - 1) * N + cc];
        }
        #pragma unroll
        for (int o = 16; o; o >>= 1) s += __shfl_xor_sync(FULL, s, o);
        if (lane == 0) out[0] = -s * (1.0f / N);
        return;
    }

    // ---------------- fast path: per-label JV Hungarian -----------------
    int n = max(r, c);
    float val = 0.f;
    if (r > 0 && c > 0) {
        float* C     = tile + w * 1024;       // C[i*32 + j]
        float* u_w   = u_all + w * 34;        // rows 1..n
        int*   p_w   = p_all + w * 34;        // col j (1..n) -> matched row (0 free)
        int*   way_w = way_all + w * 34;

        #pragma unroll 4
        for (int i = 0; i < n; i++) {
            float cv = 0.f;
            if (i < r && lane < c) cv = -g_GM[rows[w * 32 + i] * N + cols[w * 32 + lane]];
            C[i * 32 + lane] = cv;
        }
        __syncwarp();

        if (lane < n) {
            float m = 1e30f;
            #pragma unroll 4
            for (int k = 0; k < 32; k++) {
                int cidx = (k + lane) & 31;
                m = fminf(m, C[lane * 32 + cidx]);
            }
            u_w[lane + 1] = m;
        }
        __syncwarp();

        float v = 0.f;
        unsigned tmask = 0;
        if (lane < n) {
            float m = 1e30f;
            #pragma unroll 4
            for (int i = 0; i < n; i++) m = fminf(m, C[i * 32 + lane] - u_w[i + 1]);
            v = m;
            #pragma unroll 4
            for (int i = 0; i < n; i++)
                if ((C[i * 32 + lane] - u_w[i + 1]) - v <= 0.0f) tmask |= 1u << i;
        }
        __syncwarp();

        int pcol = 0;
        unsigned rmmask = 0;
        for (int i = 1; i <= n; i++) {
            bool avail = (pcol == 0) && ((tmask >> (i - 1)) & 1);
            unsigned cand = avail ? (unsigned)lane : 0xffffffffu;
            unsigned cm = __reduce_min_sync(FULL, cand);
            if (cm != 0xffffffffu) {
                if ((int)cm == lane) pcol = i;
                rmmask |= 1u << (i - 1);
            }
        }
        p_w[lane + 1] = pcol;
        __syncwarp();
        float u_match = pcol ? u_w[pcol] : 0.f;

        for (int f = 1; f <= n; f++) {
            if (rmmask & (1u << (f - 1))) continue;
            float uf = u_w[f];
            float d = (lane < n) ? (C[(f - 1) * 32 + lane] - uf) - v : 1e30f;
            int pred = 0;
            bool vis = false;
            int jf = 0; float Df = 0.f;

            for (int g = 0; g <= 32; g++) {
                // winner lane packed into key low bits; comparison truncated
                // to 32 ulp (deterministic; loss impact << 1e-3 gate).
                unsigned key = vis ? 0xffffffffu
                                   : ((fkey(d) & 0xFFFFFFE0u) | (unsigned)lane);
                unsigned rmin = __reduce_min_sync(FULL, key);
                int win = (int)(rmin & 31u);
                float dmin = __shfl_sync(FULL, d, win);
                int   i1   = __shfl_sync(FULL, pcol, win);
                float ui1  = __shfl_sync(FULL, u_match, win);
                if (i1 == 0) { jf = win + 1; Df = dmin; break; }
                if (lane == win) vis = true;
                float cij = C[(i1 - 1) * 32 + lane];
                if (!vis && lane < n) {
                    float cand = dmin + ((cij - ui1) - v);
                    if (cand < d) { d = cand; pred = win + 1; }
                }
            }

            if (vis) {
                u_w[pcol] += Df - d;
                u_match   += Df - d;
                v += d - Df;
            }
            if (lane == 0) u_w[f] += Df;
            way_w[lane + 1] = pred;
            __syncwarp();

            if (lane == 0 && jf) {
                int jj = jf;
                while (jj) {
                    int jp = way_w[jj];
                    p_w[jj] = (jp == 0) ? f : p_w[jp];
                    jj = jp;
                }
            }
            __syncwarp();
            int np = p_w[lane + 1];
            if (np != pcol) { pcol = np; u_match = u_w[pcol]; }
        }

        float s = 0.f;
        if (lane < n) { int pr = p_w[lane + 1]; s = C[(pr - 1) * 32 + lane]; }
        #pragma unroll
        for (int o = 16; o; o >>= 1) s += __shfl_xor_sync(FULL, s, o);
        val = -s;
    }
    if (lane == 0) vals[w] = val;
    __syncthreads();

    if (tid == 0) {
        float tot = 0.f;
        for (int L = 0; L < 16; L++) tot += vals[L];
        out[0] = tot * (1.0f / N);
    }
}

// ---------------------------------------------------------------------------
extern "C" void kernel_launch(void* const* d_in, const int* in_sizes, int n_in,
                              void* d_out, int out_size) {
    const float* f1 = (const float*)d_in[0];
    const float* f2 = (const float*)d_in[1];
    const int*   t1 = (const int*)d_in[2];
    const int*   t2 = (const int*)d_in[3];
    float* out = (float*)d_out;

    dotsq_kernel<<<dim3(1, 1, KSLICES + 8), 256>>>(f1, f2);
    gm_kernel<<<128, 128>>>(t1, t2);

    size_t smem_assign = (size_t)16 * 1024 * 4          // tiles
                       + 2 * 16 * 32 * 4                // rows, cols
                       + 3 * 16 * 34 * 4                // u, p, way
                       + 2 * 128 * 4                    // t1s, t2s
                       + 32 * 4 + 16 * 4 + 16;          // rc, vals, s_need + pad
    cudaFuncSetAttribute(assign_kernel,
                         cudaFuncAttributeMaxDynamicSharedMemorySize, (int)smem_assign);
    assign_kernel<<<1, 512, smem_assign>>>(t1, t2, out);
}

// round 17
// speedup vs baseline: 1.1882x; 1.1882x over previous
#include <cuda_runtime.h>

#define N 128
#define D 8192
#define KSLICES 128
#define KSLICE (D / KSLICES)   // 64
#define ASTRIDE 76             // smem row stride (words): conflict-free + 16B aligned

typedef unsigned long long ull;

__device__ float g_sq1[N], g_sq2[N];
__device__ float g_part[KSLICES * N * N];
__device__ float g_GM[N * N];
__device__ int   g_flag;           // nonzero => cross-label GM entry != 0

__device__ __forceinline__ unsigned tf32_rna(float x) {
    unsigned u;
    asm("cvt.rna.tf32.f32 %0, %1;" : "=r"(u) : "f"(x));
    return u;
}

// ---------------------------------------------------------------------------
// K1: fused tensor-core split-K GEMM + row norms.
// grid (1,1,136): z<128 -> 128x128 C tile, 64-K slice, mma.sync m16n8k8 tf32.
//   8 warps in 4m x 2n; warp tile 32x64 (2 m-tiles x 8 n-tiles), 64 f32 accs.
//   z>=128 -> 8 norm blocks (32 rows each, warp per 4 rows).
// ---------------------------------------------------------------------------
__global__ void __launch_bounds__(256) dotsq_kernel(const float* __restrict__ f1,
                                                    const float* __restrict__ f2) {
    if (blockIdx.z >= KSLICES) {
        // ---- norm path ----
        int flat = blockIdx.z - KSLICES;      // 0..7
        int tid  = threadIdx.x;
        int wid  = tid >> 5, lane = tid & 31;
        if (flat == 0 && tid == 0) g_flag = 0;
        #pragma unroll
        for (int rr = 0; rr < 4; rr++) {
            int row = flat * 32 + wid * 4 + rr;   // 0..255
            const float* f = (row < N) ? (f1 + (size_t)row * D)
                                       : (f2 + (size_t)(row - N) * D);
            const float4* f4 = (const float4*)f;
            float s = 0.f;
            #pragma unroll 8
            for (int it = 0; it < D / 4 / 32; it++) {
                float4 v = f4[lane + it * 32];
                s += v.x * v.x + v.y * v.y + v.z * v.z + v.w * v.w;
            }
            #pragma unroll
            for (int o = 16; o; o >>= 1) s += __shfl_xor_sync(0xffffffffu, s, o);
            if (lane == 0) { if (row < N) g_sq1[row] = s; else g_sq2[row - N] = s; }
        }
        return;
    }

    // ---- GEMM path: C[128][128] += A[128][64] * B[128][64]^T (tf32 MMA) ----
    extern __shared__ unsigned smem_u[];
    unsigned* Asm = smem_u;                    // [128][ASTRIDE]
    unsigned* Bsm = smem_u + 128 * ASTRIDE;    // [128][ASTRIDE]

    int tid  = threadIdx.x;                    // 0..255
    int lane = tid & 31, wid = tid >> 5;
    int gid  = lane >> 2;                      // 0..7
    int tig  = lane & 3;                       // 0..3
    int wm   = wid & 3;                        // warp m: rows wm*32..+31
    int wn   = wid >> 2;                       // warp n: cols wn*64..+63
    int k0   = blockIdx.z * KSLICE;

    // Stage A and B tiles (128 x 64 f32 each) as tf32 into smem.
    #pragma unroll
    for (int it = 0; it < 8; it++) {
        int idx = tid + it * 256;              // 0..2047 float4s
        int row = idx >> 4;
        int kq  = (idx & 15) * 4;
        float4 va = *(const float4*)&f1[(size_t)row * D + k0 + kq];
        float4 vb = *(const float4*)&f2[(size_t)row * D + k0 + kq];
        *(uint2*)&Asm[row * ASTRIDE + kq]     = make_uint2(tf32_rna(va.x), tf32_rna(va.y));
        *(uint2*)&Asm[row * ASTRIDE + kq + 2] = make_uint2(tf32_rna(va.z), tf32_rna(va.w));
        *(uint2*)&Bsm[row * ASTRIDE + kq]     = make_uint2(tf32_rna(vb.x), tf32_rna(vb.y));
        *(uint2*)&Bsm[row * ASTRIDE + kq + 2] = make_uint2(tf32_rna(vb.z), tf32_rna(vb.w));
    }
    __syncthreads();

    float acc[2][8][4];
    #pragma unroll
    for (int mt = 0; mt < 2; mt++)
        #pragma unroll
        for (int nt = 0; nt < 8; nt++)
            #pragma unroll
            for (int p = 0; p < 4; p++) acc[mt][nt][p] = 0.f;

    #pragma unroll
    for (int kk = 0; kk < KSLICE; kk += 8) {
        // B fragments: 8 n-tiles (col-major 8x8, k = tig, n = gid)
        unsigned bf[8][2];
        #pragma unroll
        for (int nt = 0; nt < 8; nt++) {
            int n = wn * 64 + nt * 8 + gid;
            bf[nt][0] = Bsm[n * ASTRIDE + kk + tig];
            bf[nt][1] = Bsm[n * ASTRIDE + kk + tig + 4];
        }
        // A fragments: 2 m-tiles (row-major 16x8)
        unsigned af[2][4];
        #pragma unroll
        for (int mt = 0; mt < 2; mt++) {
            int r = wm * 32 + mt * 16 + gid;
            af[mt][0] = Asm[r * ASTRIDE + kk + tig];
            af[mt][1] = Asm[(r + 8) * ASTRIDE + kk + tig];
            af[mt][2] = Asm[r * ASTRIDE + kk + tig + 4];
            af[mt][3] = Asm[(r + 8) * ASTRIDE + kk + tig + 4];
        }
        #pragma unroll
        for (int mt = 0; mt < 2; mt++)
            #pragma unroll
            for (int nt = 0; nt < 8; nt++) {
                asm("mma.sync.aligned.m16n8k8.row.col.f32.tf32.tf32.f32 "
                    "{%0,%1,%2,%3}, {%4,%5,%6,%7}, {%8,%9}, {%0,%1,%2,%3};"
                    : "+f"(acc[mt][nt][0]), "+f"(acc[mt][nt][1]),
                      "+f"(acc[mt][nt][2]), "+f"(acc[mt][nt][3])
                    : "r"(af[mt][0]), "r"(af[mt][1]), "r"(af[mt][2]), "r"(af[mt][3]),
                      "r"(bf[nt][0]), "r"(bf[nt][1]));
            }
    }

    // Epilogue: c0,c1 at (row, col..col+1); c2,c3 at (row+8, ...)
    float* outp = &g_part[blockIdx.z * (N * N)];
    #pragma unroll
    for (int mt = 0; mt < 2; mt++) {
        int row = wm * 32 + mt * 16 + gid;
        #pragma unroll
        for (int nt = 0; nt < 8; nt++) {
            int col = wn * 64 + nt * 8 + 2 * tig;
            *(float2*)&outp[(size_t)row * N + col]       = make_float2(acc[mt][nt][0], acc[mt][nt][1]);
            *(float2*)&outp[(size_t)(row + 8) * N + col] = make_float2(acc[mt][nt][2], acc[mt][nt][3]);
        }
    }
}

// ---------------------------------------------------------------------------
// K2: finalize GM[i][j]; flag if any cross-label GM entry is nonzero.
// ---------------------------------------------------------------------------
__global__ void gm_kernel(const int* __restrict__ t1, const int* __restrict__ t2) {
    int idx = blockIdx.x * 128 + threadIdx.x;
    int i = idx >> 7, j = idx & (N - 1);
    float dot = 0.f;
    #pragma unroll 16
    for (int s = 0; s < KSLICES; s++) dot += g_part[s * (N * N) + idx];
    float d2 = g_sq1[i] - 2.f * dot + g_sq2[j];
    bool same = (t1[i] == t2[j]);
    float gm = same ? fmaxf(0.f, d2) : fmaxf(0.f, 200.f - d2);
    g_GM[idx] = gm;
    if (!same && gm != 0.f) atomicOr(&g_flag, 1);
}

// ---------------------------------------------------------------------------
// order-preserving float -> u32 key for min reductions
// ---------------------------------------------------------------------------
__device__ __forceinline__ unsigned fkey(float f) {
    unsigned u = __float_as_uint(f);
    return (u & 0x80000000u) ? ~u : (u | 0x80000000u);
}

// ---------------------------------------------------------------------------
// K3: block-decomposed assignment (one warp per label, 16 warps in one CTA).
// Dijkstra step: winner lane packed into the REDUX key (no ballot). Warp 0
// runs the full 128x128 fallback if the precondition fails.
// ---------------------------------------------------------------------------
__global__ void assign_kernel(const int* __restrict__ t1, const int* __restrict__ t2,
                              float* __restrict__ out) {
    extern __shared__ unsigned char raw[];
    float* tile    = (float*)raw;                 // 16 * 1024 floats (64 KB)
    int*   rows    = (int*)(tile + 16 * 1024);    // 16 * 32 (fallback: rm_s)
    int*   cols    = rows + 16 * 32;              // 16 * 32
    float* u_all   = (float*)(cols + 16 * 32);    // 16 * 34 (fallback: u_s)
    int*   p_all   = (int*)(u_all + 16 * 34);     // 16 * 34 (fallback: p_s)
    int*   way_all = p_all + 16 * 34;             // 16 * 34 (fallback: way_s)
    int*   t1s     = way_all + 16 * 34;           // 128
    int*   t2s     = t1s + 128;                   // 128
    int*   rc      = t2s + 128;                   // 32
    float* vals    = (float*)(rc + 32);           // 16
    int*   s_need  = (int*)(vals + 16);           // 1

    const unsigned FULL = 0xffffffffu;
    int tid = threadIdx.x, lane = tid & 31, w = tid >> 5;

    if (tid < 128) { t1s[tid] = t1[tid]; t2s[tid] = t2[tid]; }
    __syncthreads();

    int r = 0, c = 0;
    #pragma unroll
    for (int ch = 0; ch < 4; ch++) {
        int e1 = t1s[ch * 32 + lane];
        unsigned b1 = __ballot_sync(FULL, e1 == w);
        if (e1 == w) {
            int pos = r + __popc(b1 & ((1u << lane) - 1u));
            if (pos < 32) rows[w * 32 + pos] = ch * 32 + lane;
        }
        r += __popc(b1);
        int e2 = t2s[ch * 32 + lane];
        unsigned b2 = __ballot_sync(FULL, e2 == w);
        if (e2 == w) {
            int pos = c + __popc(b2 & ((1u << lane) - 1u));
            if (pos < 32) cols[w * 32 + pos] = ch * 32 + lane;
        }
        c += __popc(b2);
    }
    if (lane == 0) { rc[w * 2] = r; rc[w * 2 + 1] = c; }
    __syncthreads();

    if (tid == 0) {
        int need = (g_flag != 0);
        int sr = 0, sc = 0;
        for (int L = 0; L < 16; L++) {
            int rr = rc[L * 2], cc = rc[L * 2 + 1];
            sr += rr; sc += cc;
            if (rr > 32 || cc > 32) need = 1;
        }
        if (sr != N || sc != N) need = 1;
        s_need[0] = need;
    }
    __syncthreads();

    // ---------------- fallback: full 128x128 single-warp Hungarian ----------
    if (s_need[0]) {
        if (w != 0) return;
        float* cost  = tile;
        float* u_s   = u_all;
        int*   p_s   = p_all;
        int*   way_s = way_all;
        int*   rm_s  = rows;

        for (int idx = lane; idx < N * N; idx += 32) cost[idx] = -g_GM[idx];
        for (int idx = lane; idx <= N; idx += 32) { p_s[idx] = 0; way_s[idx] = 0; rm_s[idx] = 0; }
        __syncwarp();

        #pragma unroll
        for (int t = 0; t < 4; t++) {
            int rr = lane + 32 * t;
            float m = 1e30f;
            #pragma unroll 4
            for (int cc = 0; cc < N; cc++) {
                int ccc = (cc + lane) & (N - 1);
                m = fminf(m, cost[rr * N + ccc]);
            }
            u_s[rr + 1] = m;
        }
        __syncwarp();

        float v4[4];
        #pragma unroll
        for (int t = 0; t < 4; t++) {
            int cc = lane + 32 * t;
            float m = 1e30f;
            for (int rr = 0; rr < N; rr++) m = fminf(m, cost[rr * N + cc] - u_s[rr + 1]);
            v4[t] = m;
        }
        __syncwarp();

        for (int i = 1; i <= N; i++) {
            unsigned cand = 0xffffffffu;
            float ui = u_s[i];
            #pragma unroll
            for (int t = 0; t < 4; t++) {
                int cc = lane + 32 * t;
                if (p_s[cc + 1] == 0) {
                    float cur = (cost[(i - 1) * N + cc] - ui) - v4[t];
                    if (cur <= 0.0f) cand = min(cand, (unsigned)cc);
                }
            }
            unsigned cm = __reduce_min_sync(FULL, cand);
            if (cm != 0xffffffffu && lane == 0) { p_s[cm + 1] = i; rm_s[i] = 1; }
            __syncwarp();
        }

        for (int i = 1; i <= N; i++) {
            if (rm_s[i]) continue;
            float minv[4] = {1e30f, 1e30f, 1e30f, 1e30f};
            unsigned usedmask = 0;
            if (lane == 0) p_s[0] = i;
            int j0 = 0;
            __syncwarp();

            for (int guard = 0; guard < N + 2; guard++) {
                if (j0 > 0) {
                    int cc = j0 - 1;
                    if ((cc & 31) == lane) usedmask |= 1u << (cc >> 5);
                }
                int i0 = p_s[j0];
                float ui0 = u_s[i0];
                float best = 1e30f; int bestc = 0;
                #pragma unroll
                for (int t = 0; t < 4; t++) {
                    if (!((usedmask >> t) & 1)) {
                        int cc = lane + 32 * t;
                        float cur = (cost[(i0 - 1) * N + cc] - ui0) - v4[t];
                        if (cur < minv[t]) { minv[t] = cur; way_s[cc + 1] = j0; }
                        if (minv[t] < best) { best = minv[t]; bestc = cc; }
                    }
                }
                unsigned key = fkey(best);
                unsigned rmin = __reduce_min_sync(FULL, key);
                unsigned ball = __ballot_sync(FULL, key == rmin);
                int win = __ffs(ball) - 1;
                float delta = __shfl_sync(FULL, best, win);
                int j1 = __shfl_sync(FULL, bestc, win) + 1;

                #pragma unroll
                for (int t = 0; t < 4; t++) {
                    if ((usedmask >> t) & 1) {
                        v4[t] -= delta;
                        int pr = p_s[lane + 32 * t + 1];
                        u_s[pr] += delta;
                    } else {
                        minv[t] -= delta;
                    }
                }
                if (lane == 0) u_s[i] += delta;
                j0 = j1;
                __syncwarp();
                if (p_s[j0] == 0) break;
            }

            if (lane == 0) {
                int jj = j0;
                while (jj) { int j1 = way_s[jj]; p_s[jj] = p_s[j1]; jj = j1; }
                rm_s[i] = 1;
            }
            __syncwarp();
        }

        float s = 0.f;
        #pragma unroll
        for (int t = 0; t < 4; t++) {
            int cc = lane + 32 * t;
            int rr = p_s[cc + 1];
            s += cost[(rr - 1) * N + cc];
        }
        #pragma unroll
        for (int o = 16; o; o >>= 1) s += __shfl_xor_sync(FULL, s, o);
        if (lane == 0) out[0] = -s * (1.0f / N);
        return;
    }

    // ---------------- fast path: per-label JV Hungarian -----------------
    int n = max(r, c);
    float val = 0.f;
    if (r > 0 && c > 0) {
        float* C     = tile + w * 1024;       // C[i*32 + j]
        float* u_w   = u_all + w * 34;        // rows 1..n
        int*   p_w   = p_all + w * 34;        // col j (1..n) -> matched row (0 free)
        int*   way_w = way_all + w * 34;

        #pragma unroll 4
        for (int i = 0; i < n; i++) {
            float cv = 0.f;
            if (i < r && lane < c) cv = -g_GM[rows[w * 32 + i] * N + cols[w * 32 + lane]];
            C[i * 32 + lane] = cv;
        }
        __syncwarp();

        if (lane < n) {
            float m = 1e30f;
            #pragma unroll 4
            for (int k = 0; k < 32; k++) {
                int cidx = (k + lane) & 31;
                m = fminf(m, C[lane * 32 + cidx]);
            }
            u_w[lane + 1] = m;
        }
        __syncwarp();

        float v = 0.f;
        unsigned tmask = 0;
        if (lane < n) {
            float m = 1e30f;
            #pragma unroll 4
            for (int i = 0; i < n; i++) m = fminf(m, C[i * 32 + lane] - u_w[i + 1]);
            v = m;
            #pragma unroll 4
            for (int i = 0; i < n; i++)
                if ((C[i * 32 + lane] - u_w[i + 1]) - v <= 0.0f) tmask |= 1u << i;
        }
        __syncwarp();

        int pcol = 0;
        unsigned rmmask = 0;
        for (int i = 1; i <= n; i++) {
            bool avail = (pcol == 0) && ((tmask >> (i - 1)) & 1);
            unsigned cand = avail ? (unsigned)lane : 0xffffffffu;
            unsigned cm = __reduce_min_sync(FULL, cand);
            if (cm != 0xffffffffu) {
                if ((int)cm == lane) pcol = i;
                rmmask |= 1u << (i - 1);
            }
        }
        p_w[lane + 1] = pcol;
        __syncwarp();
        float u_match = pcol ? u_w[pcol] : 0.f;

        for (int f = 1; f <= n; f++) {
            if (rmmask & (1u << (f - 1))) continue;
            float uf = u_w[f];
            float d = (lane < n) ? (C[(f - 1) * 32 + lane] - uf) - v : 1e30f;
            int pred = 0;
            bool vis = false;
            int jf = 0; float Df = 0.f;

            for (int g = 0; g <= 32; g++) {
                unsigned key = vis ? 0xffffffffu
                                   : ((fkey(d) & 0xFFFFFFE0u) | (unsigned)lane);
                unsigned rmin = __reduce_min_sync(FULL, key);
                int win = (int)(rmin & 31u);
                float dmin = __shfl_sync(FULL, d, win);
                int   i1   = __shfl_sync(FULL, pcol, win);
                float ui1  = __shfl_sync(FULL, u_match, win);
                if (i1 == 0) { jf = win + 1; Df = dmin; break; }
                if (lane == win) vis = true;
                float cij = C[(i1 - 1) * 32 + lane];
                if (!vis && lane < n) {
                    float cand = dmin + ((cij - ui1) - v);
                    if (cand < d) { d = cand; pred = win + 1; }
                }
            }

            if (vis) {
                u_w[pcol] += Df - d;
                u_match   += Df - d;
                v += d - Df;
            }
            if (lane == 0) u_w[f] += Df;
            way_w[lane + 1] = pred;
            __syncwarp();

            if (lane == 0 && jf) {
                int jj = jf;
                while (jj) {
                    int jp = way_w[jj];
                    p_w[jj] = (jp == 0) ? f : p_w[jp];
                    jj = jp;
                }
            }
            __syncwarp();
            int np = p_w[lane + 1];
            if (np != pcol) { pcol = np; u_match = u_w[pcol]; }
        }

        float s = 0.f;
        if (lane < n) { int pr = p_w[lane + 1]; s = C[(pr - 1) * 32 + lane]; }
        #pragma unroll
        for (int o = 16; o; o >>= 1) s += __shfl_xor_sync(FULL, s, o);
        val = -s;
    }
    if (lane == 0) vals[w] = val;
    __syncthreads();

    if (tid == 0) {
        float tot = 0.f;
        for (int L = 0; L < 16; L++) tot += vals[L];
        out[0] = tot * (1.0f / N);
    }
}

// ---------------------------------------------------------------------------
extern "C" void kernel_launch(void* const* d_in, const int* in_sizes, int n_in,
                              void* d_out, int out_size) {
    const float* f1 = (const float*)d_in[0];
    const float* f2 = (const float*)d_in[1];
    const int*   t1 = (const int*)d_in[2];
    const int*   t2 = (const int*)d_in[3];
    float* out = (float*)d_out;

    size_t smem_dot = (size_t)2 * 128 * ASTRIDE * 4;    // 77824 B
    cudaFuncSetAttribute(dotsq_kernel,
                         cudaFuncAttributeMaxDynamicSharedMemorySize, (int)smem_dot);
    dotsq_kernel<<<dim3(1, 1, KSLICES + 8), 256, smem_dot>>>(f1, f2);

    gm_kernel<<<128, 128>>>(t1, t2);

    size_t smem_assign = (size_t)16 * 1024 * 4          // tiles
                       + 2 * 16 * 32 * 4                // rows, cols
                       + 3 * 16 * 34 * 4                // u, p, way
                       + 2 * 128 * 4                    // t1s, t2s
                       + 32 * 4 + 16 * 4 + 16;          // rc, vals, s_need + pad
    cudaFuncSetAttribute(assign_kernel,
                         cudaFuncAttributeMaxDynamicSharedMemorySize, (int)smem_assign);
    assign_kernel<<<1, 512, smem_assign>>>(t1, t2, out);
}